// round 16
// baseline (speedup 1.0000x reference)
#include <cuda_runtime.h>

#define NN 50000
#define EE 1600000
#define GRID 608          // 4 blocks/SM × 152 SMs (GB300)
#define NTHR 256
#define NWARP (GRID * NTHR / 32)   // 4864
#define SEG 168                    // edges per segment; 2 segments per warp

// ---------------- scratch (device globals) ----------------------------------
__device__ float g_h[NN * 64];
__device__ float g_agg[NN * 64];
__device__ float g_acc[NN * 64];
__device__ float g_w[4 * (size_t)EE];   // per-edge weights, SoA: [head][edge]
__device__ float g_asrc[NN * 4];
__device__ float g_adst[NN * 4];
__device__ float g_sum[NN * 4];
__device__ int   g_cursor[NN];
__device__ int2  g_edge[EE];      // packed (src,dst), dst-sorted
__device__ float g_stat[128];     // raw BN sums/sumsq
__device__ int   g_part[GRID];
__device__ int   g_partpre[GRID];
__device__ int   g_tilec[3];      // GEMM work-stealing counters (zeroed in P0)
__device__ volatile int g_bar_count;
__device__ volatile int g_bar_gen;

__device__ __forceinline__ float neg_inf() { return __int_as_float(0xff800000); }
__device__ __forceinline__ float lrelu(float e) { return fmaxf(e, 0.2f * e); }

// ---------------- grid-wide barrier (all blocks co-resident) ----------------
__device__ __forceinline__ void gridsync() {
    __syncthreads();
    if (threadIdx.x == 0) {
        __threadfence();
        int gen = g_bar_gen;
        if (atomicAdd((int*)&g_bar_count, 1) == GRID - 1) {
            g_bar_count = 0;
            __threadfence();
            g_bar_gen = gen + 1;
        } else {
            while (g_bar_gen == gen) { __nanosleep(32); }
        }
        __threadfence();
    }
    __syncthreads();
}

// ---------------- GEMM phase: work-stealing tiles + BN-prep + alpha epilogue -
template <int K, int NO, bool BN, int H>
__device__ void gemm_phase(float* sm, float* bnsc, float* bnsh, int* s_tile, int* ctr,
                           const float* __restrict__ A,
                           const float* __restrict__ W, float* __restrict__ C,
                           const float* __restrict__ a_s, const float* __restrict__ a_d,
                           const float* __restrict__ bn_g, const float* __restrict__ bn_b) {
    float (*As)[36] = (float(*)[36])sm;          // 64*36 = 2304 floats
    float (*Ws)[64] = (float(*)[64])(sm + 2304); // 32*64 = 2048 floats
    const int tid = threadIdx.x;
    const int ty = tid >> 4;
    const int tx = tid & 15;
    const int lr = tid >> 3;
    const int lc = (tid & 7) * 4;
    const int ntile = (NN + 63) / 64;

    if (BN && tid < 64) {
        float mean = g_stat[tid] * (1.0f / NN);
        float var = g_stat[64 + tid] * (1.0f / NN) - mean * mean;
        float sc = bn_g[tid] * rsqrtf(var + 1e-5f);
        bnsc[tid] = sc;
        bnsh[tid] = bn_b[tid] - mean * sc;
    }
    // zero softmax denominators for this layer's aggregation
    {
        float4 z = make_float4(0.f, 0.f, 0.f, 0.f);
        float4* s4 = reinterpret_cast<float4*>(g_sum);
        for (int i = blockIdx.x * NTHR + tid; i < NN; i += GRID * NTHR) s4[i] = z;
    }
    __syncthreads();

    for (;;) {
        if (tid == 0) *s_tile = atomicAdd(ctr, 1);
        __syncthreads();
        const int tile = *s_tile;
        if (tile >= ntile) break;
        const int m0 = tile * 64;
        float acc[4][4] = {};
        for (int kt = 0; kt < K; kt += 32) {
            float4 sc, sh;
            if (BN) {
                sc = *reinterpret_cast<const float4*>(&bnsc[kt + lc]);
                sh = *reinterpret_cast<const float4*>(&bnsh[kt + lc]);
            }
#pragma unroll
            for (int rr = 0; rr < 64; rr += 32) {
                int row = m0 + lr + rr;
                float4 v = make_float4(0.f, 0.f, 0.f, 0.f);
                if (row < NN)
                    v = *reinterpret_cast<const float4*>(A + (size_t)row * K + kt + lc);
                if (BN) {
                    v.x = fmaxf(v.x * sc.x + sh.x, 0.f);
                    v.y = fmaxf(v.y * sc.y + sh.y, 0.f);
                    v.z = fmaxf(v.z * sc.z + sh.z, 0.f);
                    v.w = fmaxf(v.w * sc.w + sh.w, 0.f);
                }
                *reinterpret_cast<float4*>(&As[lr + rr][lc]) = v;
            }
#pragma unroll
            for (int kk = 0; kk < 32; kk += 16) {
                int k = ty + kk;
                int c = tx * 4;
                float4 v = make_float4(0.f, 0.f, 0.f, 0.f);
                if (NO == 64 || c < NO)
                    v = *reinterpret_cast<const float4*>(W + (size_t)(kt + k) * NO + c);
                *reinterpret_cast<float4*>(&Ws[k][c]) = v;
            }
            __syncthreads();
#pragma unroll
            for (int k = 0; k < 32; k++) {
                float a0 = As[ty * 4 + 0][k];
                float a1 = As[ty * 4 + 1][k];
                float a2 = As[ty * 4 + 2][k];
                float a3 = As[ty * 4 + 3][k];
                float4 b = *reinterpret_cast<const float4*>(&Ws[k][tx * 4]);
                acc[0][0] += a0 * b.x; acc[0][1] += a0 * b.y; acc[0][2] += a0 * b.z; acc[0][3] += a0 * b.w;
                acc[1][0] += a1 * b.x; acc[1][1] += a1 * b.y; acc[1][2] += a1 * b.z; acc[1][3] += a1 * b.w;
                acc[2][0] += a2 * b.x; acc[2][1] += a2 * b.y; acc[2][2] += a2 * b.z; acc[2][3] += a2 * b.w;
                acc[3][0] += a3 * b.x; acc[3][1] += a3 * b.y; acc[3][2] += a3 * b.z; acc[3][3] += a3 * b.w;
            }
            __syncthreads();
        }
#pragma unroll
        for (int i = 0; i < 4; i++) {
            int row = m0 + ty * 4 + i;
            if (row < NN && (NO == 64 || tx * 4 < NO)) {
                float4 v = make_float4(acc[i][0], acc[i][1], acc[i][2], acc[i][3]);
                *reinterpret_cast<float4*>(C + (size_t)row * NO + tx * 4) = v;
            }
        }
        const bool colok = (NO == 64) || (tx * 4 < NO);
        float4 av = make_float4(0.f, 0.f, 0.f, 0.f), dv = av;
        if (colok) {
            av = *reinterpret_cast<const float4*>(a_s + tx * 4);
            dv = *reinterpret_cast<const float4*>(a_d + tx * 4);
        }
#pragma unroll
        for (int i = 0; i < 4; i++) {
            float ps = acc[i][0] * av.x + acc[i][1] * av.y + acc[i][2] * av.z + acc[i][3] * av.w;
            float pd = acc[i][0] * dv.x + acc[i][1] * dv.y + acc[i][2] * dv.z + acc[i][3] * dv.w;
            ps += __shfl_xor_sync(0xffffffffu, ps, 1);
            pd += __shfl_xor_sync(0xffffffffu, pd, 1);
            ps += __shfl_xor_sync(0xffffffffu, ps, 2);
            pd += __shfl_xor_sync(0xffffffffu, pd, 2);
            int row = m0 + ty * 4 + i;
            if (H == 4) {
                if ((tx & 3) == 0 && row < NN) {
                    g_asrc[row * 4 + (tx >> 2)] = ps;
                    g_adst[row * 4 + (tx >> 2)] = pd;
                }
            } else {
                ps += __shfl_xor_sync(0xffffffffu, ps, 4);
                pd += __shfl_xor_sync(0xffffffffu, pd, 4);
                ps += __shfl_xor_sync(0xffffffffu, ps, 8);
                pd += __shfl_xor_sync(0xffffffffu, pd, 8);
                if (tx == 0 && row < NN) {
                    g_asrc[row] = ps;
                    g_adst[row] = pd;
                }
            }
        }
    }
}

// ---------------- per-edge weight precompute (lane-parallel, SoA output) ----
__device__ void wgt4_phase() {
    const int gt = blockIdx.x * NTHR + threadIdx.x;
    if (gt < 128) g_stat[gt] = 0.f;   // re-zero BN stat for upcoming post4
    for (int e = gt; e < EE; e += GRID * NTHR) {
        int2 ed = g_edge[e];
        float4 av = *reinterpret_cast<const float4*>(&g_asrc[ed.x * 4]);
        float4 dv = *reinterpret_cast<const float4*>(&g_adst[ed.y * 4]);
        g_w[e]                  = __expf(lrelu(av.x + dv.x));
        g_w[(size_t)EE + e]     = __expf(lrelu(av.y + dv.y));
        g_w[2 * (size_t)EE + e] = __expf(lrelu(av.z + dv.z));
        g_w[3 * (size_t)EE + e] = __expf(lrelu(av.w + dv.w));
    }
}

// ---------------- edge aggregation: dual-segment interleaved ----------------
// Each warp owns two independent 168-edge segments; per iteration it loads a
// 4-edge sub-chunk from each (B's loads overlap A's compute → 2× MLP, halved
// exposed L2 latency). Lane owns channels (2*lane, 2*lane+1), head = lane>>3.
__device__ void eagg4_phase(const float* __restrict__ h) {
    const int lane = threadIdx.x & 31;
    const int w = (blockIdx.x * NTHR + threadIdx.x) >> 5;
    const int cc = 2 * lane;          // channel pair base (8B aligned)
    const int head = lane >> 3;       // 0..3
    const bool sslane = (lane & 7) == 0;
    const float* __restrict__ wrow = &g_w[(size_t)head * EE];

    const int sA0 = (2 * w) * SEG;
    if (sA0 >= EE) return;
    const int sA1 = min(sA0 + SEG, EE);
    const int sB0 = sA0 + SEG;
    const int sB1 = min(sB0 + SEG, EE);
    const bool hasB = sB0 < EE;

    float aAx = 0.f, aAy = 0.f, ssA = 0.f;
    int dA = g_edge[sA0].y;
    float aBx = 0.f, aBy = 0.f, ssB = 0.f;
    int dB = hasB ? g_edge[sB0].y : 0;

    for (int it = 0; it < SEG; it += 4) {
        const int baseA = sA0 + it;
        const int baseB = sB0 + it;
        const bool doA = baseA < sA1;   // uniform across warp
        const bool doB = baseB < sB1;
        int sa[4], da[4], sb[4], db[4];
        float wa[4], wb[4];
        float2 ha[4], hb[4];
        if (doA) {
            const int4* e4 = reinterpret_cast<const int4*>(&g_edge[baseA]);
            int4 q0 = e4[0], q1 = e4[1];
            sa[0] = q0.x; da[0] = q0.y; sa[1] = q0.z; da[1] = q0.w;
            sa[2] = q1.x; da[2] = q1.y; sa[3] = q1.z; da[3] = q1.w;
            float4 wv = *reinterpret_cast<const float4*>(&wrow[baseA]);
            wa[0] = wv.x; wa[1] = wv.y; wa[2] = wv.z; wa[3] = wv.w;
#pragma unroll
            for (int j = 0; j < 4; j++)
                ha[j] = *reinterpret_cast<const float2*>(&h[(size_t)sa[j] * 64 + cc]);
        }
        if (doB) {
            const int4* e4 = reinterpret_cast<const int4*>(&g_edge[baseB]);
            int4 q0 = e4[0], q1 = e4[1];
            sb[0] = q0.x; db[0] = q0.y; sb[1] = q0.z; db[1] = q0.w;
            sb[2] = q1.x; db[2] = q1.y; sb[3] = q1.z; db[3] = q1.w;
            float4 wv = *reinterpret_cast<const float4*>(&wrow[baseB]);
            wb[0] = wv.x; wb[1] = wv.y; wb[2] = wv.z; wb[3] = wv.w;
#pragma unroll
            for (int j = 0; j < 4; j++)
                hb[j] = *reinterpret_cast<const float2*>(&h[(size_t)sb[j] * 64 + cc]);
        }
        if (doA) {
#pragma unroll
            for (int j = 0; j < 4; j++) {
                if (da[j] != dA) {
                    atomicAdd(reinterpret_cast<float2*>(&g_acc[(size_t)dA * 64 + cc]),
                              make_float2(aAx, aAy));
                    if (sslane) atomicAdd(&g_sum[dA * 4 + head], ssA);
                    aAx = aAy = ssA = 0.f;
                    dA = da[j];
                }
                aAx += wa[j] * ha[j].x;
                aAy += wa[j] * ha[j].y;
                ssA += wa[j];
            }
        }
        if (doB) {
#pragma unroll
            for (int j = 0; j < 4; j++) {
                if (db[j] != dB) {
                    atomicAdd(reinterpret_cast<float2*>(&g_acc[(size_t)dB * 64 + cc]),
                              make_float2(aBx, aBy));
                    if (sslane) atomicAdd(&g_sum[dB * 4 + head], ssB);
                    aBx = aBy = ssB = 0.f;
                    dB = db[j];
                }
                aBx += wb[j] * hb[j].x;
                aBy += wb[j] * hb[j].y;
                ssB += wb[j];
            }
        }
    }
    atomicAdd(reinterpret_cast<float2*>(&g_acc[(size_t)dA * 64 + cc]),
              make_float2(aAx, aAy));
    if (sslane) atomicAdd(&g_sum[dA * 4 + head], ssA);
    if (hasB) {
        atomicAdd(reinterpret_cast<float2*>(&g_acc[(size_t)dB * 64 + cc]),
                  make_float2(aBx, aBy));
        if (sslane) atomicAdd(&g_sum[dB * 4 + head], ssB);
    }
}

// H=1 C=40: dual-segment, inline exp, channel pairs on lanes 0..19.
__device__ void eagg1_phase(const float* __restrict__ h) {
    const int lane = threadIdx.x & 31;
    const int w = (blockIdx.x * NTHR + threadIdx.x) >> 5;
    const int cc = 2 * lane;
    const bool act = lane < 20;       // 40 channels

    const int sA0 = (2 * w) * SEG;
    if (sA0 >= EE) return;
    const int sA1 = min(sA0 + SEG, EE);
    const int sB0 = sA0 + SEG;
    const int sB1 = min(sB0 + SEG, EE);
    const bool hasB = sB0 < EE;

    float aAx = 0.f, aAy = 0.f, ssA = 0.f;
    int dA = g_edge[sA0].y;
    float aBx = 0.f, aBy = 0.f, ssB = 0.f;
    int dB = hasB ? g_edge[sB0].y : 0;

    for (int it = 0; it < SEG; it += 4) {
        const int baseA = sA0 + it;
        const int baseB = sB0 + it;
        const bool doA = baseA < sA1;
        const bool doB = baseB < sB1;
        int sa[4], da[4], sb[4], db[4];
        float wa[4], wb[4];
        float2 ha[4], hb[4];
        if (doA) {
            const int4* e4 = reinterpret_cast<const int4*>(&g_edge[baseA]);
            int4 q0 = e4[0], q1 = e4[1];
            sa[0] = q0.x; da[0] = q0.y; sa[1] = q0.z; da[1] = q0.w;
            sa[2] = q1.x; da[2] = q1.y; sa[3] = q1.z; da[3] = q1.w;
#pragma unroll
            for (int j = 0; j < 4; j++)
                ha[j] = act ? *reinterpret_cast<const float2*>(&h[(size_t)sa[j] * 40 + cc])
                            : make_float2(0.f, 0.f);
#pragma unroll
            for (int j = 0; j < 4; j++)
                wa[j] = __expf(lrelu(g_asrc[sa[j]] + g_adst[da[j]]));
        }
        if (doB) {
            const int4* e4 = reinterpret_cast<const int4*>(&g_edge[baseB]);
            int4 q0 = e4[0], q1 = e4[1];
            sb[0] = q0.x; db[0] = q0.y; sb[1] = q0.z; db[1] = q0.w;
            sb[2] = q1.x; db[2] = q1.y; sb[3] = q1.z; db[3] = q1.w;
#pragma unroll
            for (int j = 0; j < 4; j++)
                hb[j] = act ? *reinterpret_cast<const float2*>(&h[(size_t)sb[j] * 40 + cc])
                            : make_float2(0.f, 0.f);
#pragma unroll
            for (int j = 0; j < 4; j++)
                wb[j] = __expf(lrelu(g_asrc[sb[j]] + g_adst[db[j]]));
        }
        if (doA) {
#pragma unroll
            for (int j = 0; j < 4; j++) {
                if (da[j] != dA) {
                    if (act)
                        atomicAdd(reinterpret_cast<float2*>(&g_acc[(size_t)dA * 64 + cc]),
                                  make_float2(aAx, aAy));
                    if (lane == 0) atomicAdd(&g_sum[dA * 4], ssA);
                    aAx = aAy = ssA = 0.f;
                    dA = da[j];
                }
                aAx += wa[j] * ha[j].x;
                aAy += wa[j] * ha[j].y;
                ssA += wa[j];
            }
        }
        if (doB) {
#pragma unroll
            for (int j = 0; j < 4; j++) {
                if (db[j] != dB) {
                    if (act)
                        atomicAdd(reinterpret_cast<float2*>(&g_acc[(size_t)dB * 64 + cc]),
                                  make_float2(aBx, aBy));
                    if (lane == 0) atomicAdd(&g_sum[dB * 4], ssB);
                    aBx = aBy = ssB = 0.f;
                    dB = db[j];
                }
                aBx += wb[j] * hb[j].x;
                aBy += wb[j] * hb[j].y;
                ssB += wb[j];
            }
        }
    }
    if (act)
        atomicAdd(reinterpret_cast<float2*>(&g_acc[(size_t)dA * 64 + cc]),
                  make_float2(aAx, aAy));
    if (lane == 0) atomicAdd(&g_sum[dA * 4], ssA);
    if (hasB) {
        if (act)
            atomicAdd(reinterpret_cast<float2*>(&g_acc[(size_t)dB * 64 + cc]),
                      make_float2(aBx, aBy));
        if (lane == 0) atomicAdd(&g_sum[dB * 4], ssB);
    }
}

// ---------------- post phases ------------------------------------------------
__device__ void post4_phase(float* sm, const float* __restrict__ h,
                            const float* __restrict__ bias, float* __restrict__ out) {
    const int c = threadIdx.x & 63;    // constant per thread (stride % 64 == 0)
    const int head = c >> 4;
    const float bs = bias[c];
    float s_acc = 0.f, q_acc = 0.f;
    for (int idx = blockIdx.x * NTHR + threadIdx.x; idx < NN * 64; idx += GRID * NTHR) {
        int v = idx >> 6;
        float ws = __expf(lrelu(g_asrc[v * 4 + head] + g_adst[v * 4 + head]));
        float o = (g_acc[idx] + ws * h[idx]) / (g_sum[v * 4 + head] + ws + 1e-16f) + bs;
        out[idx] = o;
        g_acc[idx] = 0.f;
        s_acc += o;
        q_acc += o * o;
    }
    float* shs = sm;
    float* shq = sm + 256;
    shs[threadIdx.x] = s_acc;
    shq[threadIdx.x] = q_acc;
    __syncthreads();
    if (threadIdx.x < 64) {
        float s = shs[threadIdx.x] + shs[threadIdx.x + 64] + shs[threadIdx.x + 128] + shs[threadIdx.x + 192];
        float q = shq[threadIdx.x] + shq[threadIdx.x + 64] + shq[threadIdx.x + 128] + shq[threadIdx.x + 192];
        atomicAdd(&g_stat[threadIdx.x], s);
        atomicAdd(&g_stat[64 + threadIdx.x], q);
    }
    __syncthreads();
}

__device__ void post1_phase(const float* __restrict__ h, const float* __restrict__ bias,
                            float* __restrict__ out) {
    const int lane = threadIdx.x & 31;
    const int warp0 = (blockIdx.x * NTHR + threadIdx.x) >> 5;
    const int c0 = lane, c1 = lane + 32;
    const bool use1 = lane < 8;
    for (int gw = warp0; gw < NN; gw += NWARP) {
        float ws = __expf(lrelu(g_asrc[gw] + g_adst[gw]));
        float inv = 1.f / (g_sum[gw * 4] + ws + 1e-16f);
        float a0 = g_acc[(size_t)gw * 64 + c0];
        float a1 = use1 ? g_acc[(size_t)gw * 64 + c1] : 0.f;
        float o0 = (a0 + ws * h[(size_t)gw * 40 + c0]) * inv + bias[c0];
        float o1 = use1 ? ((a1 + ws * h[(size_t)gw * 40 + c1]) * inv + bias[c1]) : neg_inf();
        float m = fmaxf(o0, o1);
#pragma unroll
        for (int off = 16; off; off >>= 1) m = fmaxf(m, __shfl_xor_sync(0xffffffffu, m, off));
        float se = __expf(o0 - m) + (use1 ? __expf(o1 - m) : 0.f);
#pragma unroll
        for (int off = 16; off; off >>= 1) se += __shfl_xor_sync(0xffffffffu, se, off);
        float ls = __logf(se);
        out[(size_t)gw * 40 + c0] = o0 - m - ls;
        if (use1) out[(size_t)gw * 40 + c1] = o1 - m - ls;
    }
}

// ---------------- THE mega-kernel --------------------------------------------
__global__ __launch_bounds__(NTHR, 4) void k_mega(
    const float* __restrict__ x, const int* __restrict__ ei,
    const float* __restrict__ W0, const float* __restrict__ as0, const float* __restrict__ ad0,
    const float* __restrict__ b0, const float* __restrict__ g0, const float* __restrict__ be0,
    const float* __restrict__ W1, const float* __restrict__ as1, const float* __restrict__ ad1,
    const float* __restrict__ b1, const float* __restrict__ g1, const float* __restrict__ be1,
    const float* __restrict__ W2, const float* __restrict__ as2, const float* __restrict__ ad2,
    const float* __restrict__ b2, float* __restrict__ out) {
    __shared__ float smbuf[4480];
    __shared__ float bnsc[64], bnsh[64];
    __shared__ int s_tile;
    const int tid = threadIdx.x;
    const int gt = blockIdx.x * NTHR + tid;

    // P0: zero scratch (g_sum zeroed per-layer inside gemm_phase)
    {
        float4 z = make_float4(0.f, 0.f, 0.f, 0.f);
        float4* a4 = reinterpret_cast<float4*>(g_acc);
        for (int i = gt; i < NN * 16; i += GRID * NTHR) a4[i] = z;
        for (int i = gt; i < NN; i += GRID * NTHR) g_cursor[i] = 0;
        if (gt < 128) g_stat[gt] = 0.f;
        if (gt < 3) g_tilec[gt] = 0;
    }
    gridsync();

    // P1: count in-degrees
    for (int e = gt; e < EE; e += GRID * NTHR)
        atomicAdd(&g_cursor[ei[EE + e]], 1);
    gridsync();

    // P2: per-block local exclusive scan of counts
    const int CH = (NN + GRID - 1) / GRID;   // 83
    const int start = blockIdx.x * CH;
    int* si = (int*)smbuf;
    for (int i = tid; i < CH; i += NTHR)
        si[i] = (start + i < NN) ? g_cursor[start + i] : 0;
    __syncthreads();
    if (tid == 0) {
        int run = 0;
        for (int i = 0; i < CH; i++) { int v = si[i]; si[i] = run; run += v; }
        si[CH] = run;
        g_part[blockIdx.x] = run;
    }
    __syncthreads();
    gridsync();

    // P3: block 0 scans block totals
    if (blockIdx.x == 0) {
        int* sp = (int*)(smbuf + 2304);
        for (int i = tid; i < GRID; i += NTHR) sp[i] = g_part[i];
        __syncthreads();
        if (tid == 0) {
            int run = 0;
            for (int i = 0; i < GRID; i++) { int v = sp[i]; sp[i] = run; run += v; }
        }
        __syncthreads();
        for (int i = tid; i < GRID; i += NTHR) g_partpre[i] = sp[i];
    }
    gridsync();

    // P4: write scatter cursors
    {
        const int base = g_partpre[blockIdx.x];
        for (int i = tid; i < CH; i += NTHR) {
            int v = start + i;
            if (v < NN) g_cursor[v] = base + si[i];
        }
    }
    gridsync();

    // P5: scatter edges into CSR order (dst-sorted, packed int2)
    for (int e = gt; e < EE; e += GRID * NTHR) {
        int s = ei[e];
        int d = ei[EE + e];
        int pos = atomicAdd(&g_cursor[d], 1);
        g_edge[pos] = make_int2(s, d);
    }
    gridsync();

    // ---- layer 0 ----
    gemm_phase<128, 64, false, 4>(smbuf, bnsc, bnsh, &s_tile, &g_tilec[0],
                                  x, W0, g_h, as0, ad0, g0, be0);
    gridsync();
    wgt4_phase();
    gridsync();
    eagg4_phase(g_h);
    gridsync();
    post4_phase(smbuf, g_h, b0, g_agg);
    gridsync();

    // ---- layer 1 ----
    gemm_phase<64, 64, true, 4>(smbuf, bnsc, bnsh, &s_tile, &g_tilec[1],
                                g_agg, W1, g_h, as1, ad1, g0, be0);
    gridsync();
    wgt4_phase();
    gridsync();
    eagg4_phase(g_h);
    gridsync();
    post4_phase(smbuf, g_h, b1, g_agg);
    gridsync();

    // ---- layer 2 ----
    gemm_phase<64, 40, true, 1>(smbuf, bnsc, bnsh, &s_tile, &g_tilec[2],
                                g_agg, W2, g_h, as2, ad2, g1, be1);
    gridsync();
    eagg1_phase(g_h);
    gridsync();
    post1_phase(g_h, b2, out);
}

// ---------------- launch ------------------------------------------------------
extern "C" void kernel_launch(void* const* d_in, const int* in_sizes, int n_in,
                              void* d_out, int out_size) {
    const float* x   = (const float*)d_in[0];
    const int*   ei  = (const int*)d_in[1];
    const float* W0  = (const float*)d_in[2];
    const float* as0 = (const float*)d_in[3];
    const float* ad0 = (const float*)d_in[4];
    const float* b0  = (const float*)d_in[5];
    const float* g0  = (const float*)d_in[6];
    const float* be0 = (const float*)d_in[7];
    const float* W1  = (const float*)d_in[8];
    const float* as1 = (const float*)d_in[9];
    const float* ad1 = (const float*)d_in[10];
    const float* b1  = (const float*)d_in[11];
    const float* g1  = (const float*)d_in[12];
    const float* be1 = (const float*)d_in[13];
    const float* W2  = (const float*)d_in[14];
    const float* as2 = (const float*)d_in[15];
    const float* ad2 = (const float*)d_in[16];
    const float* b2  = (const float*)d_in[17];
    float* out = (float*)d_out;

    k_mega<<<GRID, NTHR>>>(x, ei, W0, as0, ad0, b0, g0, be0,
                           W1, as1, ad1, b1, g1, be1,
                           W2, as2, ad2, b2, out);
}

// round 17
// speedup vs baseline: 1.1356x; 1.1356x over previous
#include <cuda_runtime.h>

#define NN 50000
#define EE 1600000
#define GRID 608          // 4 blocks/SM × 152 SMs (GB300)
#define NTHR 256
#define NWARP (GRID * NTHR / 32)   // 4864
#define EPW 336                    // edges per warp (mult of 8; 336*4864 ≥ EE)
#define CH 83                      // nodes per block for CSR scan (83*608 ≥ NN)

// ---------------- scratch (device globals) ----------------------------------
__device__ float g_h[NN * 64];
__device__ float g_agg[NN * 64];
__device__ float g_acc[NN * 64];
__device__ float g_w[4 * (size_t)EE];   // per-edge weights, SoA: [head][edge]
__device__ float g_asrc[NN * 4];
__device__ float g_adst[NN * 4];
__device__ float g_sum[NN * 4];
__device__ int   g_cursor[NN];
__device__ int2  g_edge[EE];      // packed (src,dst), dst-sorted
__device__ float g_stat[128];     // raw BN sums/sumsq
__device__ int   g_part[GRID];
__device__ int   g_tilec[3];      // GEMM work-stealing counters (zeroed in P0)
__device__ volatile int g_bar_count;
__device__ volatile int g_bar_gen;

__device__ __forceinline__ float neg_inf() { return __int_as_float(0xff800000); }
__device__ __forceinline__ float lrelu(float e) { return fmaxf(e, 0.2f * e); }

// ---------------- grid-wide barrier (all blocks co-resident) ----------------
__device__ __forceinline__ void gridsync() {
    __syncthreads();
    if (threadIdx.x == 0) {
        __threadfence();
        int gen = g_bar_gen;
        if (atomicAdd((int*)&g_bar_count, 1) == GRID - 1) {
            g_bar_count = 0;
            __threadfence();
            g_bar_gen = gen + 1;
        } else {
            while (g_bar_gen == gen) { __nanosleep(32); }
        }
        __threadfence();
    }
    __syncthreads();
}

// ---------------- GEMM phase: work-stealing tiles + BN-prep + alpha epilogue -
template <int K, int NO, bool BN, int H>
__device__ void gemm_phase(float* sm, float* bnsc, float* bnsh, int* s_tile, int* ctr,
                           const float* __restrict__ A,
                           const float* __restrict__ W, float* __restrict__ C,
                           const float* __restrict__ a_s, const float* __restrict__ a_d,
                           const float* __restrict__ bn_g, const float* __restrict__ bn_b) {
    float (*As)[36] = (float(*)[36])sm;          // 64*36 = 2304 floats
    float (*Ws)[64] = (float(*)[64])(sm + 2304); // 32*64 = 2048 floats
    const int tid = threadIdx.x;
    const int ty = tid >> 4;
    const int tx = tid & 15;
    const int lr = tid >> 3;
    const int lc = (tid & 7) * 4;
    const int ntile = (NN + 63) / 64;

    if (BN && tid < 64) {
        float mean = g_stat[tid] * (1.0f / NN);
        float var = g_stat[64 + tid] * (1.0f / NN) - mean * mean;
        float sc = bn_g[tid] * rsqrtf(var + 1e-5f);
        bnsc[tid] = sc;
        bnsh[tid] = bn_b[tid] - mean * sc;
    }
    // zero softmax denominators for this layer's aggregation
    {
        float4 z = make_float4(0.f, 0.f, 0.f, 0.f);
        float4* s4 = reinterpret_cast<float4*>(g_sum);
        for (int i = blockIdx.x * NTHR + tid; i < NN; i += GRID * NTHR) s4[i] = z;
    }
    __syncthreads();

    for (;;) {
        if (tid == 0) *s_tile = atomicAdd(ctr, 1);
        __syncthreads();
        const int tile = *s_tile;
        if (tile >= ntile) break;
        const int m0 = tile * 64;
        float acc[4][4] = {};
        for (int kt = 0; kt < K; kt += 32) {
            float4 sc, sh;
            if (BN) {
                sc = *reinterpret_cast<const float4*>(&bnsc[kt + lc]);
                sh = *reinterpret_cast<const float4*>(&bnsh[kt + lc]);
            }
#pragma unroll
            for (int rr = 0; rr < 64; rr += 32) {
                int row = m0 + lr + rr;
                float4 v = make_float4(0.f, 0.f, 0.f, 0.f);
                if (row < NN)
                    v = *reinterpret_cast<const float4*>(A + (size_t)row * K + kt + lc);
                if (BN) {
                    v.x = fmaxf(v.x * sc.x + sh.x, 0.f);
                    v.y = fmaxf(v.y * sc.y + sh.y, 0.f);
                    v.z = fmaxf(v.z * sc.z + sh.z, 0.f);
                    v.w = fmaxf(v.w * sc.w + sh.w, 0.f);
                }
                *reinterpret_cast<float4*>(&As[lr + rr][lc]) = v;
            }
#pragma unroll
            for (int kk = 0; kk < 32; kk += 16) {
                int k = ty + kk;
                int c = tx * 4;
                float4 v = make_float4(0.f, 0.f, 0.f, 0.f);
                if (NO == 64 || c < NO)
                    v = *reinterpret_cast<const float4*>(W + (size_t)(kt + k) * NO + c);
                *reinterpret_cast<float4*>(&Ws[k][c]) = v;
            }
            __syncthreads();
#pragma unroll
            for (int k = 0; k < 32; k++) {
                float a0 = As[ty * 4 + 0][k];
                float a1 = As[ty * 4 + 1][k];
                float a2 = As[ty * 4 + 2][k];
                float a3 = As[ty * 4 + 3][k];
                float4 b = *reinterpret_cast<const float4*>(&Ws[k][tx * 4]);
                acc[0][0] += a0 * b.x; acc[0][1] += a0 * b.y; acc[0][2] += a0 * b.z; acc[0][3] += a0 * b.w;
                acc[1][0] += a1 * b.x; acc[1][1] += a1 * b.y; acc[1][2] += a1 * b.z; acc[1][3] += a1 * b.w;
                acc[2][0] += a2 * b.x; acc[2][1] += a2 * b.y; acc[2][2] += a2 * b.z; acc[2][3] += a2 * b.w;
                acc[3][0] += a3 * b.x; acc[3][1] += a3 * b.y; acc[3][2] += a3 * b.z; acc[3][3] += a3 * b.w;
            }
            __syncthreads();
        }
#pragma unroll
        for (int i = 0; i < 4; i++) {
            int row = m0 + ty * 4 + i;
            if (row < NN && (NO == 64 || tx * 4 < NO)) {
                float4 v = make_float4(acc[i][0], acc[i][1], acc[i][2], acc[i][3]);
                *reinterpret_cast<float4*>(C + (size_t)row * NO + tx * 4) = v;
            }
        }
        const bool colok = (NO == 64) || (tx * 4 < NO);
        float4 av = make_float4(0.f, 0.f, 0.f, 0.f), dv = av;
        if (colok) {
            av = *reinterpret_cast<const float4*>(a_s + tx * 4);
            dv = *reinterpret_cast<const float4*>(a_d + tx * 4);
        }
#pragma unroll
        for (int i = 0; i < 4; i++) {
            float ps = acc[i][0] * av.x + acc[i][1] * av.y + acc[i][2] * av.z + acc[i][3] * av.w;
            float pd = acc[i][0] * dv.x + acc[i][1] * dv.y + acc[i][2] * dv.z + acc[i][3] * dv.w;
            ps += __shfl_xor_sync(0xffffffffu, ps, 1);
            pd += __shfl_xor_sync(0xffffffffu, pd, 1);
            ps += __shfl_xor_sync(0xffffffffu, ps, 2);
            pd += __shfl_xor_sync(0xffffffffu, pd, 2);
            int row = m0 + ty * 4 + i;
            if (H == 4) {
                if ((tx & 3) == 0 && row < NN) {
                    g_asrc[row * 4 + (tx >> 2)] = ps;
                    g_adst[row * 4 + (tx >> 2)] = pd;
                }
            } else {
                ps += __shfl_xor_sync(0xffffffffu, ps, 4);
                pd += __shfl_xor_sync(0xffffffffu, pd, 4);
                ps += __shfl_xor_sync(0xffffffffu, ps, 8);
                pd += __shfl_xor_sync(0xffffffffu, pd, 8);
                if (tx == 0 && row < NN) {
                    g_asrc[row] = ps;
                    g_adst[row] = pd;
                }
            }
        }
    }
}

// ---------------- per-edge weight precompute (lane-parallel, SoA output) ----
__device__ void wgt4_phase() {
    const int gt = blockIdx.x * NTHR + threadIdx.x;
    if (gt < 128) g_stat[gt] = 0.f;   // re-zero BN stat for upcoming post4
    for (int e = gt; e < EE; e += GRID * NTHR) {
        int2 ed = g_edge[e];
        float4 av = *reinterpret_cast<const float4*>(&g_asrc[ed.x * 4]);
        float4 dv = *reinterpret_cast<const float4*>(&g_adst[ed.y * 4]);
        g_w[e]                  = __expf(lrelu(av.x + dv.x));
        g_w[(size_t)EE + e]     = __expf(lrelu(av.y + dv.y));
        g_w[2 * (size_t)EE + e] = __expf(lrelu(av.z + dv.z));
        g_w[3 * (size_t)EE + e] = __expf(lrelu(av.w + dv.w));
    }
}

// ---------------- edge aggregation: vectorized metadata + float2 atomics ----
// (R15 shape — proven best. Lane owns channels (2*lane, 2*lane+1).)
__device__ void eagg4_phase(const float* __restrict__ h) {
    const int lane = threadIdx.x & 31;
    const int w = (blockIdx.x * NTHR + threadIdx.x) >> 5;
    const int e0 = w * EPW;
    if (e0 >= EE) return;
    const int e1 = min(e0 + EPW, EE);
    const int cc = 2 * lane;          // channel pair base (8B aligned)
    const int head = lane >> 3;       // 0..3
    const bool sslane = (lane & 7) == 0;
    const float* __restrict__ wrow = &g_w[(size_t)head * EE];

    float accx = 0.f, accy = 0.f, ss = 0.f;
    int dcur = g_edge[e0].y;

    for (int base = e0; base < e1; base += 8) {   // e0,e1 multiples of 8
        const int4* e4 = reinterpret_cast<const int4*>(&g_edge[base]);
        int4 q0 = e4[0], q1 = e4[1], q2 = e4[2], q3 = e4[3];   // 4 broadcast LDG.128
        int s[8] = {q0.x, q0.z, q1.x, q1.z, q2.x, q2.z, q3.x, q3.z};
        int d[8] = {q0.y, q0.w, q1.y, q1.w, q2.y, q2.w, q3.y, q3.w};
        float4 wa = *reinterpret_cast<const float4*>(&wrow[base]);
        float4 wb = *reinterpret_cast<const float4*>(&wrow[base + 4]);
        float wv[8] = {wa.x, wa.y, wa.z, wa.w, wb.x, wb.y, wb.z, wb.w};
        float2 hv[8];
#pragma unroll
        for (int j = 0; j < 8; j++)
            hv[j] = *reinterpret_cast<const float2*>(&h[(size_t)s[j] * 64 + cc]);
#pragma unroll
        for (int j = 0; j < 8; j++) {
            if (d[j] != dcur) {       // uniform branch
                atomicAdd(reinterpret_cast<float2*>(&g_acc[(size_t)dcur * 64 + cc]),
                          make_float2(accx, accy));
                if (sslane) atomicAdd(&g_sum[dcur * 4 + head], ss);
                accx = accy = ss = 0.f;
                dcur = d[j];
            }
            accx += wv[j] * hv[j].x;
            accy += wv[j] * hv[j].y;
            ss += wv[j];
        }
    }
    atomicAdd(reinterpret_cast<float2*>(&g_acc[(size_t)dcur * 64 + cc]),
              make_float2(accx, accy));
    if (sslane) atomicAdd(&g_sum[dcur * 4 + head], ss);
}

// H=1 C=40: inline exp (1 MUFU/edge), channel pairs on lanes 0..19.
__device__ void eagg1_phase(const float* __restrict__ h) {
    const int lane = threadIdx.x & 31;
    const int w = (blockIdx.x * NTHR + threadIdx.x) >> 5;
    const int e0 = w * EPW;
    if (e0 >= EE) return;
    const int e1 = min(e0 + EPW, EE);
    const int cc = 2 * lane;
    const bool act = lane < 20;       // 40 channels

    float accx = 0.f, accy = 0.f, ss = 0.f;
    int dcur = g_edge[e0].y;

    for (int base = e0; base < e1; base += 8) {
        const int4* e4 = reinterpret_cast<const int4*>(&g_edge[base]);
        int4 q0 = e4[0], q1 = e4[1], q2 = e4[2], q3 = e4[3];
        int s[8] = {q0.x, q0.z, q1.x, q1.z, q2.x, q2.z, q3.x, q3.z};
        int d[8] = {q0.y, q0.w, q1.y, q1.w, q2.y, q2.w, q3.y, q3.w};
        float wv[8];
#pragma unroll
        for (int j = 0; j < 8; j++)
            wv[j] = __expf(lrelu(g_asrc[s[j]] + g_adst[d[j]]));  // broadcast loads
        float2 hv[8];
#pragma unroll
        for (int j = 0; j < 8; j++)
            hv[j] = act ? *reinterpret_cast<const float2*>(&h[(size_t)s[j] * 40 + cc])
                        : make_float2(0.f, 0.f);
#pragma unroll
        for (int j = 0; j < 8; j++) {
            if (d[j] != dcur) {
                if (act)
                    atomicAdd(reinterpret_cast<float2*>(&g_acc[(size_t)dcur * 64 + cc]),
                              make_float2(accx, accy));
                if (lane == 0) atomicAdd(&g_sum[dcur * 4], ss);
                accx = accy = ss = 0.f;
                dcur = d[j];
            }
            accx += wv[j] * hv[j].x;
            accy += wv[j] * hv[j].y;
            ss += wv[j];
        }
    }
    if (act)
        atomicAdd(reinterpret_cast<float2*>(&g_acc[(size_t)dcur * 64 + cc]),
                  make_float2(accx, accy));
    if (lane == 0) atomicAdd(&g_sum[dcur * 4], ss);
}

// ---------------- post phases ------------------------------------------------
__device__ void post4_phase(float* sm, const float* __restrict__ h,
                            const float* __restrict__ bias, float* __restrict__ out) {
    const int c = threadIdx.x & 63;    // constant per thread (stride % 64 == 0)
    const int head = c >> 4;
    const float bs = bias[c];
    float s_acc = 0.f, q_acc = 0.f;
    for (int idx = blockIdx.x * NTHR + threadIdx.x; idx < NN * 64; idx += GRID * NTHR) {
        int v = idx >> 6;
        float ws = __expf(lrelu(g_asrc[v * 4 + head] + g_adst[v * 4 + head]));
        float o = (g_acc[idx] + ws * h[idx]) / (g_sum[v * 4 + head] + ws + 1e-16f) + bs;
        out[idx] = o;
        g_acc[idx] = 0.f;
        s_acc += o;
        q_acc += o * o;
    }
    float* shs = sm;
    float* shq = sm + 256;
    shs[threadIdx.x] = s_acc;
    shq[threadIdx.x] = q_acc;
    __syncthreads();
    if (threadIdx.x < 64) {
        float s = shs[threadIdx.x] + shs[threadIdx.x + 64] + shs[threadIdx.x + 128] + shs[threadIdx.x + 192];
        float q = shq[threadIdx.x] + shq[threadIdx.x + 64] + shq[threadIdx.x + 128] + shq[threadIdx.x + 192];
        atomicAdd(&g_stat[threadIdx.x], s);
        atomicAdd(&g_stat[64 + threadIdx.x], q);
    }
    __syncthreads();
}

__device__ void post1_phase(const float* __restrict__ h, const float* __restrict__ bias,
                            float* __restrict__ out) {
    const int lane = threadIdx.x & 31;
    const int warp0 = (blockIdx.x * NTHR + threadIdx.x) >> 5;
    const int c0 = lane, c1 = lane + 32;
    const bool use1 = lane < 8;
    for (int gw = warp0; gw < NN; gw += NWARP) {
        float ws = __expf(lrelu(g_asrc[gw] + g_adst[gw]));
        float inv = 1.f / (g_sum[gw * 4] + ws + 1e-16f);
        float a0 = g_acc[(size_t)gw * 64 + c0];
        float a1 = use1 ? g_acc[(size_t)gw * 64 + c1] : 0.f;
        float o0 = (a0 + ws * h[(size_t)gw * 40 + c0]) * inv + bias[c0];
        float o1 = use1 ? ((a1 + ws * h[(size_t)gw * 40 + c1]) * inv + bias[c1]) : neg_inf();
        float m = fmaxf(o0, o1);
#pragma unroll
        for (int off = 16; off; off >>= 1) m = fmaxf(m, __shfl_xor_sync(0xffffffffu, m, off));
        float se = __expf(o0 - m) + (use1 ? __expf(o1 - m) : 0.f);
#pragma unroll
        for (int off = 16; off; off >>= 1) se += __shfl_xor_sync(0xffffffffu, se, off);
        float ls = __logf(se);
        out[(size_t)gw * 40 + c0] = o0 - m - ls;
        if (use1) out[(size_t)gw * 40 + c1] = o1 - m - ls;
    }
}

// ---------------- THE mega-kernel --------------------------------------------
__global__ __launch_bounds__(NTHR, 4) void k_mega(
    const float* __restrict__ x, const int* __restrict__ ei,
    const float* __restrict__ W0, const float* __restrict__ as0, const float* __restrict__ ad0,
    const float* __restrict__ b0, const float* __restrict__ g0, const float* __restrict__ be0,
    const float* __restrict__ W1, const float* __restrict__ as1, const float* __restrict__ ad1,
    const float* __restrict__ b1, const float* __restrict__ g1, const float* __restrict__ be1,
    const float* __restrict__ W2, const float* __restrict__ as2, const float* __restrict__ ad2,
    const float* __restrict__ b2, float* __restrict__ out) {
    __shared__ float smbuf[4480];
    __shared__ float bnsc[64], bnsh[64];
    __shared__ int s_tile;
    const int tid = threadIdx.x;
    const int gt = blockIdx.x * NTHR + tid;

    // P0: zero scratch (g_sum zeroed per-layer inside gemm_phase)
    {
        float4 z = make_float4(0.f, 0.f, 0.f, 0.f);
        float4* a4 = reinterpret_cast<float4*>(g_acc);
        for (int i = gt; i < NN * 16; i += GRID * NTHR) a4[i] = z;
        for (int i = gt; i < NN; i += GRID * NTHR) g_cursor[i] = 0;
        if (gt < 128) g_stat[gt] = 0.f;
        if (gt < 3) g_tilec[gt] = 0;
    }
    gridsync();

    // P1: count in-degrees
    for (int e = gt; e < EE; e += GRID * NTHR)
        atomicAdd(&g_cursor[ei[EE + e]], 1);
    gridsync();

    // P2: per-block PARALLEL exclusive scan of this block's CH node counts
    const int start = blockIdx.x * CH;
    int* si = (int*)smbuf;                       // [0..128) inclusive-scan buffer
    {
        int v = 0;
        if (tid < CH && start + tid < NN) v = g_cursor[start + tid];
        if (tid < 128) si[tid] = v;
        __syncthreads();
#pragma unroll
        for (int off = 1; off < 128; off <<= 1) {
            int add = 0;
            if (tid < 128 && tid >= off) add = si[tid - off];
            __syncthreads();
            if (tid < 128) si[tid] += add;
            __syncthreads();
        }
        if (tid == 0) g_part[blockIdx.x] = si[127];   // block total
    }
    gridsync();

    // P3+P4 merged: EVERY block scans all 608 partials (double-buffered
    // Hillis-Steele in smem) and writes its own nodes' scatter cursors.
    {
        int* spA = (int*)smbuf + 512;
        int* spB = spA + GRID;
        for (int i = tid; i < GRID; i += NTHR) spA[i] = g_part[i];
        __syncthreads();
        int* src = spA;
        int* dst = spB;
        for (int off = 1; off < GRID; off <<= 1) {
            for (int i = tid; i < GRID; i += NTHR)
                dst[i] = src[i] + (i >= off ? src[i - off] : 0);
            __syncthreads();
            int* t = src; src = dst; dst = t;
        }
        const int base = (blockIdx.x > 0) ? src[blockIdx.x - 1] : 0;  // exclusive
        if (tid < CH) {
            int v = start + tid;
            if (v < NN) g_cursor[v] = base + (tid > 0 ? si[tid - 1] : 0);
        }
    }
    gridsync();

    // P5: scatter edges into CSR order (dst-sorted, packed int2)
    for (int e = gt; e < EE; e += GRID * NTHR) {
        int s = ei[e];
        int d = ei[EE + e];
        int pos = atomicAdd(&g_cursor[d], 1);
        g_edge[pos] = make_int2(s, d);
    }
    gridsync();

    // ---- layer 0 ----
    gemm_phase<128, 64, false, 4>(smbuf, bnsc, bnsh, &s_tile, &g_tilec[0],
                                  x, W0, g_h, as0, ad0, g0, be0);
    gridsync();
    wgt4_phase();
    gridsync();
    eagg4_phase(g_h);
    gridsync();
    post4_phase(smbuf, g_h, b0, g_agg);
    gridsync();

    // ---- layer 1 ----
    gemm_phase<64, 64, true, 4>(smbuf, bnsc, bnsh, &s_tile, &g_tilec[1],
                                g_agg, W1, g_h, as1, ad1, g0, be0);
    gridsync();
    wgt4_phase();
    gridsync();
    eagg4_phase(g_h);
    gridsync();
    post4_phase(smbuf, g_h, b1, g_agg);
    gridsync();

    // ---- layer 2 ----
    gemm_phase<64, 40, true, 1>(smbuf, bnsc, bnsh, &s_tile, &g_tilec[2],
                                g_agg, W2, g_h, as2, ad2, g1, be1);
    gridsync();
    eagg1_phase(g_h);
    gridsync();
    post1_phase(g_h, b2, out);
}

// ---------------- launch ------------------------------------------------------
extern "C" void kernel_launch(void* const* d_in, const int* in_sizes, int n_in,
                              void* d_out, int out_size) {
    const float* x   = (const float*)d_in[0];
    const int*   ei  = (const int*)d_in[1];
    const float* W0  = (const float*)d_in[2];
    const float* as0 = (const float*)d_in[3];
    const float* ad0 = (const float*)d_in[4];
    const float* b0  = (const float*)d_in[5];
    const float* g0  = (const float*)d_in[6];
    const float* be0 = (const float*)d_in[7];
    const float* W1  = (const float*)d_in[8];
    const float* as1 = (const float*)d_in[9];
    const float* ad1 = (const float*)d_in[10];
    const float* b1  = (const float*)d_in[11];
    const float* g1  = (const float*)d_in[12];
    const float* be1 = (const float*)d_in[13];
    const float* W2  = (const float*)d_in[14];
    const float* as2 = (const float*)d_in[15];
    const float* ad2 = (const float*)d_in[16];
    const float* b2  = (const float*)d_in[17];
    float* out = (float*)d_out;

    k_mega<<<GRID, NTHR>>>(x, ei, W0, as0, ad0, b0, g0, be0,
                           W1, as1, ad1, b1, g1, be1,
                           W2, as2, ad2, b2, out);
}